// round 3
// baseline (speedup 1.0000x reference)
#include <cuda_runtime.h>

#define BN_EPS 1e-5f

// ---------------- scratch (allocation-free rule: __device__ globals) --------
static __device__ float g_h[1024 * 2048];          //   8 MB
static __device__ float g_feats[1024 * 1024];      //   4 MB
static __device__ float g_z[128 * 1024 * 512];     // 256 MB
static __device__ float g_a0[2048], g_bb0[2048];
static __device__ float g_a1[1024], g_bb1[1024];

// --------- fold BN(eval) + bias into per-column alpha/beta ------------------
// y = (gemm + b - m) * (g / sqrt(v+eps)) + be  ==  gemm*alpha + beta
__global__ void prep_bn_kernel(const float* __restrict__ b0, const float* __restrict__ g0,
                               const float* __restrict__ be0, const float* __restrict__ m0,
                               const float* __restrict__ v0,
                               const float* __restrict__ b1, const float* __restrict__ g1,
                               const float* __restrict__ be1, const float* __restrict__ m1,
                               const float* __restrict__ v1) {
    int i = blockIdx.x * blockDim.x + threadIdx.x;
    if (i < 2048) {
        float a = g0[i] / sqrtf(v0[i] + BN_EPS);
        g_a0[i]  = a;
        g_bb0[i] = be0[i] + (b0[i] - m0[i]) * a;
    }
    if (i < 1024) {
        float a = g1[i] / sqrtf(v1[i] + BN_EPS);
        g_a1[i]  = a;
        g_bb1[i] = be1[i] + (b1[i] - m1[i]) * a;
    }
}

// ---------------- generic batched SGEMM, 128x128x8 tile, 8x8 microtile ------
// A [M,K] row-major (lda=K), B [K,N] row-major (ldb=N), C row-major with ldc.
// Per-batch (blockIdx.z) strides sA/sB/sC and beta stride sAB.
// Epilogue: v = act(v*alpha[col] + beta[col]); alpha==1 when !HAS_ALPHA.
// Requires: M%128==0, N%128==0, K%8==0 (true for all 4 stages here).
template <bool RELU, bool HAS_ALPHA>
__global__ __launch_bounds__(256, 2)
void sgemm_kernel(const float* __restrict__ A, const float* __restrict__ B,
                  float* __restrict__ C,
                  int N, int K, int ldc,
                  long long sA, long long sB, long long sC,
                  const float* __restrict__ alpha,
                  const float* __restrict__ beta, int sAB) {
    A    += (long long)blockIdx.z * sA;
    B    += (long long)blockIdx.z * sB;
    C    += (long long)blockIdx.z * sC;
    beta += (long long)blockIdx.z * sAB;

    __shared__ float As[8][128];   // transposed A tile: As[k][m]
    __shared__ float Bs[8][128];   // Bs[k][n]

    const int tid = threadIdx.x;
    const int tx = tid & 15;       // 16 col-groups of 8
    const int ty = tid >> 4;       // 16 row-groups of 8

    const int rowBase = blockIdx.y * 128;
    const int colBase = blockIdx.x * 128;

    // global->smem mapping: one float4 per thread per tile, fully coalesced
    const int aRow = tid >> 1;           // 0..127
    const int aCol = (tid & 1) * 4;      // 0 or 4
    const int bRow = tid >> 5;           // 0..7
    const int bCol = (tid & 31) * 4;     // 0..124

    const float* aPtr = A + (long long)(rowBase + aRow) * K + aCol;
    const float* bPtr = B + (long long)bRow * N + colBase + bCol;

    float acc[8][8];
#pragma unroll
    for (int i = 0; i < 8; i++)
#pragma unroll
        for (int j = 0; j < 8; j++) acc[i][j] = 0.0f;

    for (int kt = 0; kt < K; kt += 8) {
        const float4 av = *(const float4*)(aPtr + kt);
        const float4 bv = *(const float4*)(bPtr + (long long)kt * N);
        __syncthreads();               // previous tile fully consumed
        As[aCol + 0][aRow] = av.x;
        As[aCol + 1][aRow] = av.y;
        As[aCol + 2][aRow] = av.z;
        As[aCol + 3][aRow] = av.w;
        *(float4*)&Bs[bRow][bCol] = bv;
        __syncthreads();

#pragma unroll
        for (int k = 0; k < 8; k++) {
            float aFrag[8], bFrag[8];
            *(float4*)&aFrag[0] = *(const float4*)&As[k][ty * 8];
            *(float4*)&aFrag[4] = *(const float4*)&As[k][ty * 8 + 4];
            *(float4*)&bFrag[0] = *(const float4*)&Bs[k][tx * 8];
            *(float4*)&bFrag[4] = *(const float4*)&Bs[k][tx * 8 + 4];
#pragma unroll
            for (int i = 0; i < 8; i++)
#pragma unroll
                for (int j = 0; j < 8; j++)
                    acc[i][j] = fmaf(aFrag[i], bFrag[j], acc[i][j]);
        }
    }

    // -------- epilogue: per-column alpha/beta (+ReLU), float4 stores --------
    const int cCol = colBase + tx * 8;
    float alj[8], bej[8];
#pragma unroll
    for (int j = 0; j < 8; j += 4) {
        *(float4*)&bej[j] = *(const float4*)(beta + cCol + j);
        if (HAS_ALPHA) *(float4*)&alj[j] = *(const float4*)(alpha + cCol + j);
    }
#pragma unroll
    for (int i = 0; i < 8; i++) {
        const int r = rowBase + ty * 8 + i;
        float ov[8];
#pragma unroll
        for (int j = 0; j < 8; j++) {
            float v = HAS_ALPHA ? fmaf(acc[i][j], alj[j], bej[j])
                                : (acc[i][j] + bej[j]);
            if (RELU) v = fmaxf(v, 0.0f);
            ov[j] = v;
        }
        float* cRowPtr = C + (long long)r * ldc + cCol;
        *(float4*)(cRowPtr)     = *(float4*)&ov[0];
        *(float4*)(cRowPtr + 4) = *(float4*)&ov[4];
    }
}

extern "C" void kernel_launch(void* const* d_in, const int* in_sizes, int n_in,
                              void* d_out, int out_size) {
    const float* x   = (const float*)d_in[0];
    const float* W0  = (const float*)d_in[1];
    const float* b0  = (const float*)d_in[2];
    const float* g0  = (const float*)d_in[3];
    const float* be0 = (const float*)d_in[4];
    const float* m0  = (const float*)d_in[5];
    const float* v0  = (const float*)d_in[6];
    const float* W1  = (const float*)d_in[7];
    const float* b1  = (const float*)d_in[8];
    const float* g1  = (const float*)d_in[9];
    const float* be1 = (const float*)d_in[10];
    const float* m1  = (const float*)d_in[11];
    const float* v1  = (const float*)d_in[12];
    const float* HW1 = (const float*)d_in[13];
    const float* Hb1 = (const float*)d_in[14];
    const float* HW2 = (const float*)d_in[15];
    const float* Hb2 = (const float*)d_in[16];
    float* out = (float*)d_out;

    float *h, *feats, *z, *a0, *bb0, *a1, *bb1;
    cudaGetSymbolAddress((void**)&h,     g_h);
    cudaGetSymbolAddress((void**)&feats, g_feats);
    cudaGetSymbolAddress((void**)&z,     g_z);
    cudaGetSymbolAddress((void**)&a0,    g_a0);
    cudaGetSymbolAddress((void**)&bb0,   g_bb0);
    cudaGetSymbolAddress((void**)&a1,    g_a1);
    cudaGetSymbolAddress((void**)&bb1,   g_bb1);

    // 0) fold BN stats into per-column alpha/beta
    prep_bn_kernel<<<8, 256>>>(b0, g0, be0, m0, v0, b1, g1, be1, m1, v1);

    // 1) h = relu(BN(x @ W0 + b0))            [1024,200]x[200,2048]
    sgemm_kernel<true, true><<<dim3(16, 8, 1), 256>>>(
        x, W0, h, 2048, 200, 2048, 0, 0, 0, a0, bb0, 0);

    // 2) feats = relu(BN(h @ W1 + b1))        [1024,2048]x[2048,1024]
    sgemm_kernel<true, true><<<dim3(8, 8, 1), 256>>>(
        h, W1, feats, 1024, 2048, 1024, 0, 0, 0, a1, bb1, 0);

    // 3) z[n] = relu(feats @ HW1[n] + Hb1[n]) 128 x ([1024,1024]x[1024,512])
    sgemm_kernel<true, false><<<dim3(4, 8, 128), 256>>>(
        feats, HW1, z, 512, 1024, 512,
        0, 1024LL * 512, 1024LL * 512, nullptr, Hb1, 512);

    // 4) out[:,n,:] = z[n] @ HW2[n] + Hb2[n]  128 x ([1024,512]x[512,256])
    //    written directly into [B,128,256]: C_n = out + n*256, ldc = 128*256
    sgemm_kernel<false, false><<<dim3(2, 8, 128), 256>>>(
        z, HW2, out, 256, 512, 128 * 256,
        1024LL * 512, 512LL * 256, 256, nullptr, Hb2, 256);
}

// round 5
// speedup vs baseline: 2.2275x; 2.2275x over previous
#include <cuda_runtime.h>
#include <cuda_fp16.h>
#include <cstdint>

#define BN_EPS 1e-5f

// ======================= device scratch (no allocs allowed) =================
static __device__ float g_h[1024 * 2048];                 // trunk hidden
static __device__ __half g_fh[1024 * 1024];               // feats hi
static __device__ __half g_fl[1024 * 1024];               // feats lo
static __device__ __half g_w1h[128u * 512u * 1024u];      // HW1^T hi [n][N=512][K=1024]
static __device__ __half g_w1l[128u * 512u * 1024u];
static __device__ __half g_w2h[128u * 256u * 512u];       // HW2^T hi [n][N=256][K=512]
static __device__ __half g_w2l[128u * 256u * 512u];
static __device__ __half g_zh[128u * 1024u * 512u];       // z hi [n][M=1024][K=512]
static __device__ __half g_zl[128u * 1024u * 512u];
static __device__ float g_a0[2048], g_bb0[2048];
static __device__ float g_a1[1024], g_bb1[1024];

// ======================= small helpers ======================================
__device__ __forceinline__ uint32_t smem_to_u32(const void* p) {
    uint32_t a;
    asm("{ .reg .u64 t; cvta.to.shared.u64 t, %1; cvt.u32.u64 %0, t; }" : "=r"(a) : "l"(p));
    return a;
}
__device__ __forceinline__ uint32_t swz128(uint32_t off) {  // SW128 swizzle
    return off ^ ((off >> 3) & 0x70);
}
__device__ __forceinline__ void cp_async16(uint32_t dst, const void* src) {
    asm volatile("cp.async.cg.shared.global [%0], [%1], 16;" :: "r"(dst), "l"(src));
}
#define CP_COMMIT() asm volatile("cp.async.commit_group;" ::: "memory")
#define CP_WAIT(n)  asm volatile("cp.async.wait_group %0;" :: "n"(n) : "memory")

#define LDMX4(r, addr) \
    asm volatile("ldmatrix.sync.aligned.m8n8.x4.shared.b16 {%0,%1,%2,%3}, [%4];" \
        : "=r"((r)[0]), "=r"((r)[1]), "=r"((r)[2]), "=r"((r)[3]) : "r"(addr))

#define MMA_F16(d, a, b0_, b1_) \
    asm volatile("mma.sync.aligned.m16n8k16.row.col.f32.f16.f16.f32 " \
        "{%0,%1,%2,%3}, {%4,%5,%6,%7}, {%8,%9}, {%0,%1,%2,%3};" \
        : "+f"((d)[0]), "+f"((d)[1]), "+f"((d)[2]), "+f"((d)[3]) \
        : "r"((a)[0]), "r"((a)[1]), "r"((a)[2]), "r"((a)[3]), "r"(b0_), "r"(b1_))

__device__ __forceinline__ uint32_t pack_h2(__half lo16, __half hi16) {
    return ((uint32_t)__half_as_ushort(hi16) << 16) | __half_as_ushort(lo16);
}

// =========================== prep: fold BN into alpha/beta ==================
__global__ void prep_bn_kernel(const float* __restrict__ b0, const float* __restrict__ g0,
                               const float* __restrict__ be0, const float* __restrict__ m0,
                               const float* __restrict__ v0,
                               const float* __restrict__ b1, const float* __restrict__ g1,
                               const float* __restrict__ be1, const float* __restrict__ m1,
                               const float* __restrict__ v1) {
    int i = blockIdx.x * blockDim.x + threadIdx.x;
    if (i < 2048) {
        float a = g0[i] / sqrtf(v0[i] + BN_EPS);
        g_a0[i]  = a;
        g_bb0[i] = be0[i] + (b0[i] - m0[i]) * a;
    }
    if (i < 1024) {
        float a = g1[i] / sqrtf(v1[i] + BN_EPS);
        g_a1[i]  = a;
        g_bb1[i] = be1[i] + (b1[i] - m1[i]) * a;
    }
}

// ====== transpose + fp32 -> (fp16 hi, fp16 lo) for head weights =============
// in:  [head][R][C]  (R=K, C=N, row-major, C contiguous)
// out: [head][C][R]  (K-major per N-row)
__global__ void transpose_split_kernel(const float* __restrict__ in,
                                       __half* __restrict__ oh,
                                       __half* __restrict__ ol,
                                       int R, int C) {
    __shared__ float t[32][33];
    const long long hoff = (long long)blockIdx.z * R * C;
    in += hoff; oh += hoff; ol += hoff;
    const int r0 = blockIdx.y * 32, c0 = blockIdx.x * 32;
    const int tx = threadIdx.x, ty = threadIdx.y;
#pragma unroll
    for (int i = 0; i < 4; i++)
        t[ty + i * 8][tx] = in[(long long)(r0 + ty + i * 8) * C + c0 + tx];
    __syncthreads();
#pragma unroll
    for (int i = 0; i < 4; i++) {
        float v = t[tx][ty + i * 8];
        __half h = __float2half(v);
        __half l = __float2half(v - __half2float(h));
        long long o = (long long)(c0 + ty + i * 8) * R + r0 + tx;
        oh[o] = h; ol[o] = l;
    }
}

// ================= fp32 SGEMM (stages 1-2), 128x128x8, 8x8 micro ============
template <bool RELU, bool SPLIT>
__global__ __launch_bounds__(256, 2)
void sgemm_kernel(const float* __restrict__ A, const float* __restrict__ B,
                  float* __restrict__ C,
                  __half* __restrict__ Ch, __half* __restrict__ Cl,
                  int N, int K, int ldc,
                  const float* __restrict__ alpha, const float* __restrict__ beta) {
    __shared__ float As[8][128];
    __shared__ float Bs[8][128];
    const int tid = threadIdx.x;
    const int tx = tid & 15;
    const int ty = tid >> 4;
    const int rowBase = blockIdx.y * 128;
    const int colBase = blockIdx.x * 128;
    const int aRow = tid >> 1, aCol = (tid & 1) * 4;
    const int bRow = tid >> 5, bCol = (tid & 31) * 4;
    const float* aPtr = A + (long long)(rowBase + aRow) * K + aCol;
    const float* bPtr = B + (long long)bRow * N + colBase + bCol;

    float acc[8][8];
#pragma unroll
    for (int i = 0; i < 8; i++)
#pragma unroll
        for (int j = 0; j < 8; j++) acc[i][j] = 0.0f;

    for (int kt = 0; kt < K; kt += 8) {
        const float4 av = *(const float4*)(aPtr + kt);
        const float4 bv = *(const float4*)(bPtr + (long long)kt * N);
        __syncthreads();
        As[aCol + 0][aRow] = av.x; As[aCol + 1][aRow] = av.y;
        As[aCol + 2][aRow] = av.z; As[aCol + 3][aRow] = av.w;
        *(float4*)&Bs[bRow][bCol] = bv;
        __syncthreads();
#pragma unroll
        for (int k = 0; k < 8; k++) {
            float aF[8], bF[8];
            *(float4*)&aF[0] = *(const float4*)&As[k][ty * 8];
            *(float4*)&aF[4] = *(const float4*)&As[k][ty * 8 + 4];
            *(float4*)&bF[0] = *(const float4*)&Bs[k][tx * 8];
            *(float4*)&bF[4] = *(const float4*)&Bs[k][tx * 8 + 4];
#pragma unroll
            for (int i = 0; i < 8; i++)
#pragma unroll
                for (int j = 0; j < 8; j++)
                    acc[i][j] = fmaf(aF[i], bF[j], acc[i][j]);
        }
    }

    const int cCol = colBase + tx * 8;
    float alj[8], bej[8];
#pragma unroll
    for (int j = 0; j < 8; j += 4) {
        *(float4*)&bej[j] = *(const float4*)(beta + cCol + j);
        *(float4*)&alj[j] = *(const float4*)(alpha + cCol + j);
    }
#pragma unroll
    for (int i = 0; i < 8; i++) {
        const int r = rowBase + ty * 8 + i;
        float ov[8];
#pragma unroll
        for (int j = 0; j < 8; j++) {
            float v = fmaf(acc[i][j], alj[j], bej[j]);
            if (RELU) v = fmaxf(v, 0.0f);
            ov[j] = v;
        }
        if (SPLIT) {
            uint32_t hp[4], lp[4];
#pragma unroll
            for (int j = 0; j < 8; j += 2) {
                __half h0 = __float2half(ov[j]);
                __half h1 = __float2half(ov[j + 1]);
                __half l0 = __float2half(ov[j]     - __half2float(h0));
                __half l1 = __float2half(ov[j + 1] - __half2float(h1));
                hp[j >> 1] = pack_h2(h0, h1);
                lp[j >> 1] = pack_h2(l0, l1);
            }
            long long o = (long long)r * ldc + cCol;
            *(uint4*)(Ch + o) = make_uint4(hp[0], hp[1], hp[2], hp[3]);
            *(uint4*)(Cl + o) = make_uint4(lp[0], lp[1], lp[2], lp[3]);
        } else {
            float* cp = C + (long long)r * ldc + cCol;
            *(float4*)(cp)     = *(float4*)&ov[0];
            *(float4*)(cp + 4) = *(float4*)&ov[4];
        }
    }
}

// ============== mma.sync split-fp16 batched GEMM (stages 3-4) ===============
// C[M,N] = A[M,K] * B[N,K]^T with A,B given as fp16 (hi,lo); fp32 accum via
// 3-pass: Ah*Bh + Ah*Bl + Al*Bh. CTA tile 128x128, warp tile 32x64, KC=64.
// A per-head stride sA (0 => shared), lda in elements; B rows are K-major.
// Epilogue adds bias[col] (+ReLU); SPLIT re-splits to fp16 hi/lo else fp32.
static constexpr int HM_TILE   = 16384;           // 128 rows x 128 B
static constexpr int HM_BUF    = 4 * HM_TILE;     // Ah, Al, Bh, Bl
static constexpr int HM_SMEM   = 2 * HM_BUF;      // double buffer = 131072

__device__ __forceinline__ void hm_load_tile(uint32_t sdst, const __half* g,
                                             int ld, int tid) {
    // 128 rows x 8 sixteen-byte chunks, 256 threads -> 4 chunks each
#pragma unroll
    for (int u = tid; u < 1024; u += 256) {
        const int r = u >> 3, c = u & 7;
        uint32_t off = (uint32_t)(r * 128 + c * 16);
        cp_async16(sdst + swz128(off), g + (long long)r * ld + c * 8);
    }
}

template <bool RELU, bool SPLIT>
__global__ __launch_bounds__(256)
void hmma_gemm_kernel(const __half* __restrict__ Ah, const __half* __restrict__ Al,
                      long long sA, int lda,
                      const __half* __restrict__ Bh, const __half* __restrict__ Bl,
                      long long sB,
                      const float* __restrict__ bias, int sBias,
                      float* __restrict__ Cf,
                      __half* __restrict__ Ch, __half* __restrict__ Cl,
                      long long sC, int ldc, int K) {
    extern __shared__ char smem[];
    const uint32_t sb = smem_to_u32(smem);
    const int tid = threadIdx.x;
    const int lane = tid & 31;
    const int w = tid >> 5;
    const int wm = (w >> 1) * 32;       // warp row offset in CTA tile
    const int wn = (w & 1) * 64;        // warp col offset
    const int head = blockIdx.z;
    const int mBase = blockIdx.y * 128;
    const int nBase = blockIdx.x * 128;

    const __half* pAh = Ah + (long long)head * sA + (long long)mBase * lda;
    const __half* pAl = Al + (long long)head * sA + (long long)mBase * lda;
    const __half* pBh = Bh + (long long)head * sB + (long long)nBase * K;
    const __half* pBl = Bl + (long long)head * sB + (long long)nBase * K;

    float acc[2][8][4];
#pragma unroll
    for (int mi = 0; mi < 2; mi++)
#pragma unroll
        for (int n = 0; n < 8; n++)
#pragma unroll
            for (int q = 0; q < 4; q++) acc[mi][n][q] = 0.0f;

    const int nCh = K >> 6;

    // prologue: chunk 0 -> buffer 0
    hm_load_tile(sb,               pAh, lda, tid);
    hm_load_tile(sb + HM_TILE,     pAl, lda, tid);
    hm_load_tile(sb + 2 * HM_TILE, pBh, K,   tid);
    hm_load_tile(sb + 3 * HM_TILE, pBl, K,   tid);
    CP_COMMIT();

    // precomputed ldmatrix intra-tile offsets (swizzled base varies per k-step)
    const int aRowA = wm + (lane & 15);
    const int aRowB = wn + (lane & 15);
    const int cSel  = (lane >> 4);      // 0/1 -> k chunk select

    for (int c = 0; c < nCh; ++c) {
        if (c + 1 < nCh) {
            const uint32_t nb = sb + ((c + 1) & 1) * HM_BUF;
            const int kB = (c + 1) * 64;
            hm_load_tile(nb,               pAh + kB, lda, tid);
            hm_load_tile(nb + HM_TILE,     pAl + kB, lda, tid);
            hm_load_tile(nb + 2 * HM_TILE, pBh + kB, K,   tid);
            hm_load_tile(nb + 3 * HM_TILE, pBl + kB, K,   tid);
            CP_COMMIT();
            CP_WAIT(1);                  // chunk c resident
        } else {
            CP_WAIT(0);
        }
        __syncthreads();

        const uint32_t bAh = sb + (c & 1) * HM_BUF;
        const uint32_t bAl = bAh + HM_TILE;
        const uint32_t bBh = bAh + 2 * HM_TILE;
        const uint32_t bBl = bAh + 3 * HM_TILE;

#pragma unroll
        for (int ks = 0; ks < 4; ks++) {
            const int kc = ks * 2 + cSel;
            uint32_t ah[2][4], al[2][4];
#pragma unroll
            for (int mi = 0; mi < 2; mi++) {
                uint32_t ad = swz128((uint32_t)((aRowA + mi * 16) * 128 + kc * 16));
                LDMX4(ah[mi], bAh + ad);
                LDMX4(al[mi], bAl + ad);
            }
#pragma unroll
            for (int g = 0; g < 4; g++) {
                uint32_t bh[4], bl[4];
                uint32_t bd = swz128((uint32_t)((aRowB + g * 16) * 128 + kc * 16));
                LDMX4(bh, bBh + bd);
                LDMX4(bl, bBl + bd);
#pragma unroll
                for (int mi = 0; mi < 2; mi++) {
#pragma unroll
                    for (int s = 0; s < 2; s++) {
                        const int n = g * 2 + s;
                        MMA_F16(acc[mi][n], ah[mi], bh[s], bh[s + 2]);
                        MMA_F16(acc[mi][n], ah[mi], bl[s], bl[s + 2]);
                        MMA_F16(acc[mi][n], al[mi], bh[s], bh[s + 2]);
                    }
                }
            }
        }
        __syncthreads();    // buffer consumed; next iter may overwrite it
    }

    // -------------------------------- epilogue ------------------------------
    const float* bp = bias + (long long)head * sBias + nBase;
#pragma unroll
    for (int mi = 0; mi < 2; mi++) {
        const int r0 = mBase + wm + mi * 16 + (lane >> 2);
#pragma unroll
        for (int n = 0; n < 8; n++) {
            const int colL = wn + n * 8 + (lane & 3) * 2;   // CTA-local column
            const float b0 = __ldg(bp + colL);
            const float b1 = __ldg(bp + colL + 1);
#pragma unroll
            for (int rr = 0; rr < 2; rr++) {
                float v0 = acc[mi][n][rr * 2 + 0] + b0;
                float v1 = acc[mi][n][rr * 2 + 1] + b1;
                if (RELU) { v0 = fmaxf(v0, 0.0f); v1 = fmaxf(v1, 0.0f); }
                const long long o = (long long)head * sC +
                                    (long long)(r0 + rr * 8) * ldc + nBase + colL;
                if (SPLIT) {
                    __half h0 = __float2half(v0), h1 = __float2half(v1);
                    __half l0 = __float2half(v0 - __half2float(h0));
                    __half l1 = __float2half(v1 - __half2float(h1));
                    *(uint32_t*)(Ch + o) = pack_h2(h0, h1);
                    *(uint32_t*)(Cl + o) = pack_h2(l0, l1);
                } else {
                    *(float2*)(Cf + o) = make_float2(v0, v1);
                }
            }
        }
    }
}

// ================================ launcher ==================================
extern "C" void kernel_launch(void* const* d_in, const int* in_sizes, int n_in,
                              void* d_out, int out_size) {
    const float* x   = (const float*)d_in[0];
    const float* W0  = (const float*)d_in[1];
    const float* b0  = (const float*)d_in[2];
    const float* g0  = (const float*)d_in[3];
    const float* be0 = (const float*)d_in[4];
    const float* m0  = (const float*)d_in[5];
    const float* v0  = (const float*)d_in[6];
    const float* W1  = (const float*)d_in[7];
    const float* b1  = (const float*)d_in[8];
    const float* g1  = (const float*)d_in[9];
    const float* be1 = (const float*)d_in[10];
    const float* m1  = (const float*)d_in[11];
    const float* v1  = (const float*)d_in[12];
    const float* HW1 = (const float*)d_in[13];
    const float* Hb1 = (const float*)d_in[14];
    const float* HW2 = (const float*)d_in[15];
    const float* Hb2 = (const float*)d_in[16];
    float* out = (float*)d_out;

    float *h, *a0, *bb0, *a1, *bb1;
    __half *fh, *fl, *w1h, *w1l, *w2h, *w2l, *zh, *zl;
    cudaGetSymbolAddress((void**)&h,   g_h);
    cudaGetSymbolAddress((void**)&fh,  g_fh);
    cudaGetSymbolAddress((void**)&fl,  g_fl);
    cudaGetSymbolAddress((void**)&w1h, g_w1h);
    cudaGetSymbolAddress((void**)&w1l, g_w1l);
    cudaGetSymbolAddress((void**)&w2h, g_w2h);
    cudaGetSymbolAddress((void**)&w2l, g_w2l);
    cudaGetSymbolAddress((void**)&zh,  g_zh);
    cudaGetSymbolAddress((void**)&zl,  g_zl);
    cudaGetSymbolAddress((void**)&a0,  g_a0);
    cudaGetSymbolAddress((void**)&bb0, g_bb0);
    cudaGetSymbolAddress((void**)&a1,  g_a1);
    cudaGetSymbolAddress((void**)&bb1, g_bb1);

    cudaFuncSetAttribute(hmma_gemm_kernel<true, true>,
                         cudaFuncAttributeMaxDynamicSharedMemorySize, HM_SMEM);
    cudaFuncSetAttribute(hmma_gemm_kernel<false, false>,
                         cudaFuncAttributeMaxDynamicSharedMemorySize, HM_SMEM);

    // 0) fold BN into alpha/beta
    prep_bn_kernel<<<8, 256>>>(b0, g0, be0, m0, v0, b1, g1, be1, m1, v1);

    // 0b) head weights: transpose to K-major + split to fp16 hi/lo
    transpose_split_kernel<<<dim3(512 / 32, 1024 / 32, 128), dim3(32, 8)>>>(HW1, w1h, w1l, 1024, 512);
    transpose_split_kernel<<<dim3(256 / 32, 512 / 32, 128), dim3(32, 8)>>>(HW2, w2h, w2l, 512, 256);

    // 1) h = relu(BN(x @ W0 + b0))            fp32
    sgemm_kernel<true, false><<<dim3(16, 8), 256>>>(
        x, W0, h, nullptr, nullptr, 2048, 200, 2048, a0, bb0);

    // 2) feats = relu(BN(h @ W1 + b1))        fp32 -> fp16 hi/lo
    sgemm_kernel<true, true><<<dim3(8, 8), 256>>>(
        h, W1, nullptr, fh, fl, 1024, 2048, 1024, a1, bb1);

    // 3) z[n] = relu(feats @ HW1[n] + Hb1[n])  -> fp16 hi/lo [n][1024][512]
    hmma_gemm_kernel<true, true><<<dim3(4, 8, 128), 256, HM_SMEM>>>(
        fh, fl, 0LL, 1024,
        w1h, w1l, 512LL * 1024,
        Hb1, 512,
        nullptr, zh, zl, 1024LL * 512, 512, 1024);

    // 4) out[:,n,:] = z[n] @ HW2[n] + Hb2[n]   -> fp32 [1024][128][256]
    hmma_gemm_kernel<false, false><<<dim3(2, 8, 128), 256, HM_SMEM>>>(
        zh, zl, 1024LL * 512, 512,
        w2h, w2l, 256LL * 512,
        Hb2, 256,
        out, nullptr, nullptr, 256LL, 128 * 256, 512);
}

// round 6
// speedup vs baseline: 3.1367x; 1.4082x over previous
#include <cuda_runtime.h>
#include <cuda_fp16.h>
#include <cstdint>

#define BN_EPS 1e-5f

// ======================= device scratch (no allocs allowed) =================
static __device__ float g_h[1024 * 2048];                 // trunk hidden
static __device__ __half g_fh[1024 * 1024];               // feats (fp16)
static __device__ __half g_w1h[128u * 512u * 1024u];      // HW1^T hi [n][512][1024]
static __device__ __half g_w1l[128u * 512u * 1024u];      // HW1^T lo
static __device__ __half g_w2h[128u * 256u * 512u];       // HW2^T hi [n][256][512]
static __device__ __half g_w2l[128u * 256u * 512u];       // HW2^T lo
static __device__ __half g_zh[128u * 1024u * 512u];       // z (fp16) [n][1024][512]
static __device__ float g_a0[2048], g_bb0[2048];
static __device__ float g_a1[1024], g_bb1[1024];

// ======================= small helpers ======================================
__device__ __forceinline__ uint32_t smem_to_u32(const void* p) {
    uint32_t a;
    asm("{ .reg .u64 t; cvta.to.shared.u64 t, %1; cvt.u32.u64 %0, t; }" : "=r"(a) : "l"(p));
    return a;
}
__device__ __forceinline__ uint32_t swz128(uint32_t off) {  // SW128 swizzle
    return off ^ ((off >> 3) & 0x70);
}
__device__ __forceinline__ void cp_async16(uint32_t dst, const void* src) {
    asm volatile("cp.async.cg.shared.global [%0], [%1], 16;" :: "r"(dst), "l"(src));
}
#define CP_COMMIT() asm volatile("cp.async.commit_group;" ::: "memory")
#define CP_WAIT(n)  asm volatile("cp.async.wait_group %0;" :: "n"(n) : "memory")

#define LDMX4(r, addr) \
    asm volatile("ldmatrix.sync.aligned.m8n8.x4.shared.b16 {%0,%1,%2,%3}, [%4];" \
        : "=r"((r)[0]), "=r"((r)[1]), "=r"((r)[2]), "=r"((r)[3]) : "r"(addr))

#define MMA_F16(d, a, b0_, b1_) \
    asm volatile("mma.sync.aligned.m16n8k16.row.col.f32.f16.f16.f32 " \
        "{%0,%1,%2,%3}, {%4,%5,%6,%7}, {%8,%9}, {%0,%1,%2,%3};" \
        : "+f"((d)[0]), "+f"((d)[1]), "+f"((d)[2]), "+f"((d)[3]) \
        : "r"((a)[0]), "r"((a)[1]), "r"((a)[2]), "r"((a)[3]), "r"(b0_), "r"(b1_))

__device__ __forceinline__ uint32_t pack_h2(__half lo16, __half hi16) {
    return ((uint32_t)__half_as_ushort(hi16) << 16) | __half_as_ushort(lo16);
}

// =========================== prep: fold BN into alpha/beta ==================
__global__ void prep_bn_kernel(const float* __restrict__ b0, const float* __restrict__ g0,
                               const float* __restrict__ be0, const float* __restrict__ m0,
                               const float* __restrict__ v0,
                               const float* __restrict__ b1, const float* __restrict__ g1,
                               const float* __restrict__ be1, const float* __restrict__ m1,
                               const float* __restrict__ v1) {
    int i = blockIdx.x * blockDim.x + threadIdx.x;
    if (i < 2048) {
        float a = g0[i] / sqrtf(v0[i] + BN_EPS);
        g_a0[i]  = a;
        g_bb0[i] = be0[i] + (b0[i] - m0[i]) * a;
    }
    if (i < 1024) {
        float a = g1[i] / sqrtf(v1[i] + BN_EPS);
        g_a1[i]  = a;
        g_bb1[i] = be1[i] + (b1[i] - m1[i]) * a;
    }
}

// ====== transpose + fp32 -> (fp16 hi, fp16 lo) for head weights =============
// in:  [head][R][C]  (R=K, C=N, row-major) ; out: [head][C][R] (K-major)
__global__ void transpose_split_kernel(const float* __restrict__ in,
                                       __half* __restrict__ oh,
                                       __half* __restrict__ ol,
                                       int R, int C) {
    __shared__ float t[32][33];
    const long long hoff = (long long)blockIdx.z * R * C;
    in += hoff; oh += hoff; ol += hoff;
    const int r0 = blockIdx.y * 32, c0 = blockIdx.x * 32;
    const int tx = threadIdx.x, ty = threadIdx.y;
#pragma unroll
    for (int i = 0; i < 4; i++)
        t[ty + i * 8][tx] = in[(long long)(r0 + ty + i * 8) * C + c0 + tx];
    __syncthreads();
#pragma unroll
    for (int i = 0; i < 4; i++) {
        float v = t[tx][ty + i * 8];
        __half h = __float2half(v);
        __half l = __float2half(v - __half2float(h));
        long long o = (long long)(c0 + ty + i * 8) * R + r0 + tx;
        oh[o] = h; ol[o] = l;
    }
}

// ================= fp32 SGEMM (stages 1-2), 128x128x8, 8x8 micro ============
template <bool RELU, bool TOHALF>
__global__ __launch_bounds__(256, 2)
void sgemm_kernel(const float* __restrict__ A, const float* __restrict__ B,
                  float* __restrict__ C, __half* __restrict__ Ch,
                  int N, int K, int ldc,
                  const float* __restrict__ alpha, const float* __restrict__ beta) {
    __shared__ float As[8][128];
    __shared__ float Bs[8][128];
    const int tid = threadIdx.x;
    const int tx = tid & 15;
    const int ty = tid >> 4;
    const int rowBase = blockIdx.y * 128;
    const int colBase = blockIdx.x * 128;
    const int aRow = tid >> 1, aCol = (tid & 1) * 4;
    const int bRow = tid >> 5, bCol = (tid & 31) * 4;
    const float* aPtr = A + (long long)(rowBase + aRow) * K + aCol;
    const float* bPtr = B + (long long)bRow * N + colBase + bCol;

    float acc[8][8];
#pragma unroll
    for (int i = 0; i < 8; i++)
#pragma unroll
        for (int j = 0; j < 8; j++) acc[i][j] = 0.0f;

    for (int kt = 0; kt < K; kt += 8) {
        const float4 av = *(const float4*)(aPtr + kt);
        const float4 bv = *(const float4*)(bPtr + (long long)kt * N);
        __syncthreads();
        As[aCol + 0][aRow] = av.x; As[aCol + 1][aRow] = av.y;
        As[aCol + 2][aRow] = av.z; As[aCol + 3][aRow] = av.w;
        *(float4*)&Bs[bRow][bCol] = bv;
        __syncthreads();
#pragma unroll
        for (int k = 0; k < 8; k++) {
            float aF[8], bF[8];
            *(float4*)&aF[0] = *(const float4*)&As[k][ty * 8];
            *(float4*)&aF[4] = *(const float4*)&As[k][ty * 8 + 4];
            *(float4*)&bF[0] = *(const float4*)&Bs[k][tx * 8];
            *(float4*)&bF[4] = *(const float4*)&Bs[k][tx * 8 + 4];
#pragma unroll
            for (int i = 0; i < 8; i++)
#pragma unroll
                for (int j = 0; j < 8; j++)
                    acc[i][j] = fmaf(aF[i], bF[j], acc[i][j]);
        }
    }

    const int cCol = colBase + tx * 8;
    float alj[8], bej[8];
#pragma unroll
    for (int j = 0; j < 8; j += 4) {
        *(float4*)&bej[j] = *(const float4*)(beta + cCol + j);
        *(float4*)&alj[j] = *(const float4*)(alpha + cCol + j);
    }
#pragma unroll
    for (int i = 0; i < 8; i++) {
        const int r = rowBase + ty * 8 + i;
        float ov[8];
#pragma unroll
        for (int j = 0; j < 8; j++) {
            float v = fmaf(acc[i][j], alj[j], bej[j]);
            if (RELU) v = fmaxf(v, 0.0f);
            ov[j] = v;
        }
        if (TOHALF) {
            uint32_t hp[4];
#pragma unroll
            for (int j = 0; j < 8; j += 2)
                hp[j >> 1] = pack_h2(__float2half(ov[j]), __float2half(ov[j + 1]));
            *(uint4*)(Ch + (long long)r * ldc + cCol) = make_uint4(hp[0], hp[1], hp[2], hp[3]);
        } else {
            float* cp = C + (long long)r * ldc + cCol;
            *(float4*)(cp)     = *(float4*)&ov[0];
            *(float4*)(cp + 4) = *(float4*)&ov[4];
        }
    }
}

// ====== mma.sync 2-pass (B hi/lo compensated) batched GEMM (stages 3-4) =====
// C[M,N] = A[M,K] * (Bh + Bl)[N,K]^T ; A fp16, B split fp16, fp32 accum.
// CTA tile 128x128, warp tile 32x64, K-chunk 64, double buffer, 2 CTAs/SM.
static constexpr int HM_TILE = 16384;           // 128 rows x 128 B
static constexpr int HM_BUF  = 3 * HM_TILE;     // A, Bh, Bl
static constexpr int HM_SMEM = 2 * HM_BUF;      // 98304

__device__ __forceinline__ void hm_load_tile(uint32_t sdst, const __half* g,
                                             int ld, int tid) {
#pragma unroll
    for (int u = tid; u < 1024; u += 256) {
        const int r = u >> 3, c = u & 7;
        uint32_t off = (uint32_t)(r * 128 + c * 16);
        cp_async16(sdst + swz128(off), g + (long long)r * ld + c * 8);
    }
}

template <bool RELU, bool TOHALF>
__global__ __launch_bounds__(256, 2)
void hmma_gemm_kernel(const __half* __restrict__ A, long long sA, int lda,
                      const __half* __restrict__ Bh, const __half* __restrict__ Bl,
                      long long sB,
                      const float* __restrict__ bias, int sBias,
                      float* __restrict__ Cf, __half* __restrict__ Ch,
                      long long sC, int ldc, int K) {
    extern __shared__ char smem[];
    const uint32_t sb = smem_to_u32(smem);
    const int tid = threadIdx.x;
    const int lane = tid & 31;
    const int w = tid >> 5;
    const int wm = (w >> 1) * 32;       // warp row offset
    const int wn = (w & 1) * 64;        // warp col offset
    const int head = blockIdx.z;
    const int mBase = blockIdx.y * 128;
    const int nBase = blockIdx.x * 128;

    const __half* pA  = A  + (long long)head * sA + (long long)mBase * lda;
    const __half* pBh = Bh + (long long)head * sB + (long long)nBase * K;
    const __half* pBl = Bl + (long long)head * sB + (long long)nBase * K;

    float acc[2][8][4];
#pragma unroll
    for (int mi = 0; mi < 2; mi++)
#pragma unroll
        for (int n = 0; n < 8; n++)
#pragma unroll
            for (int q = 0; q < 4; q++) acc[mi][n][q] = 0.0f;

    const int nCh = K >> 6;

    // prologue: chunk 0 -> buffer 0
    hm_load_tile(sb,               pA,  lda, tid);
    hm_load_tile(sb + HM_TILE,     pBh, K,   tid);
    hm_load_tile(sb + 2 * HM_TILE, pBl, K,   tid);
    CP_COMMIT();

    const int aRowA = wm + (lane & 15);
    const int aRowB = wn + (lane & 15);
    const int cSel  = (lane >> 4);      // 0/1 -> k half select

    for (int c = 0; c < nCh; ++c) {
        if (c + 1 < nCh) {
            const uint32_t nb = sb + ((c + 1) & 1) * HM_BUF;
            const int kB = (c + 1) * 64;
            hm_load_tile(nb,               pA  + kB, lda, tid);
            hm_load_tile(nb + HM_TILE,     pBh + kB, K,   tid);
            hm_load_tile(nb + 2 * HM_TILE, pBl + kB, K,   tid);
            CP_COMMIT();
            CP_WAIT(1);                  // chunk c resident
        } else {
            CP_WAIT(0);
        }
        __syncthreads();

        const uint32_t bA  = sb + (c & 1) * HM_BUF;
        const uint32_t bBh = bA + HM_TILE;
        const uint32_t bBl = bA + 2 * HM_TILE;

#pragma unroll
        for (int ks = 0; ks < 4; ks++) {
            const int kc = ks * 2 + cSel;
            uint32_t ah[2][4];
#pragma unroll
            for (int mi = 0; mi < 2; mi++) {
                uint32_t ad = swz128((uint32_t)((aRowA + mi * 16) * 128 + kc * 16));
                LDMX4(ah[mi], bA + ad);
            }
#pragma unroll
            for (int g = 0; g < 4; g++) {
                uint32_t bh[4], bl[4];
                uint32_t bd = swz128((uint32_t)((aRowB + g * 16) * 128 + kc * 16));
                LDMX4(bh, bBh + bd);
                LDMX4(bl, bBl + bd);
#pragma unroll
                for (int mi = 0; mi < 2; mi++) {
#pragma unroll
                    for (int s = 0; s < 2; s++) {
                        const int n = g * 2 + s;
                        MMA_F16(acc[mi][n], ah[mi], bh[s], bh[s + 2]);
                        MMA_F16(acc[mi][n], ah[mi], bl[s], bl[s + 2]);
                    }
                }
            }
        }
        __syncthreads();    // buffer consumed; next iter may overwrite it
    }

    // -------------------------------- epilogue ------------------------------
    const float* bp = bias + (long long)head * sBias + nBase;
#pragma unroll
    for (int mi = 0; mi < 2; mi++) {
        const int r0 = mBase + wm + mi * 16 + (lane >> 2);
#pragma unroll
        for (int n = 0; n < 8; n++) {
            const int colL = wn + n * 8 + (lane & 3) * 2;
            const float b0 = __ldg(bp + colL);
            const float b1 = __ldg(bp + colL + 1);
#pragma unroll
            for (int rr = 0; rr < 2; rr++) {
                float v0 = acc[mi][n][rr * 2 + 0] + b0;
                float v1 = acc[mi][n][rr * 2 + 1] + b1;
                if (RELU) { v0 = fmaxf(v0, 0.0f); v1 = fmaxf(v1, 0.0f); }
                const long long o = (long long)head * sC +
                                    (long long)(r0 + rr * 8) * ldc + nBase + colL;
                if (TOHALF) {
                    *(uint32_t*)(Ch + o) = pack_h2(__float2half(v0), __float2half(v1));
                } else {
                    *(float2*)(Cf + o) = make_float2(v0, v1);
                }
            }
        }
    }
}

// ================================ launcher ==================================
extern "C" void kernel_launch(void* const* d_in, const int* in_sizes, int n_in,
                              void* d_out, int out_size) {
    const float* x   = (const float*)d_in[0];
    const float* W0  = (const float*)d_in[1];
    const float* b0  = (const float*)d_in[2];
    const float* g0  = (const float*)d_in[3];
    const float* be0 = (const float*)d_in[4];
    const float* m0  = (const float*)d_in[5];
    const float* v0  = (const float*)d_in[6];
    const float* W1  = (const float*)d_in[7];
    const float* b1  = (const float*)d_in[8];
    const float* g1  = (const float*)d_in[9];
    const float* be1 = (const float*)d_in[10];
    const float* m1  = (const float*)d_in[11];
    const float* v1  = (const float*)d_in[12];
    const float* HW1 = (const float*)d_in[13];
    const float* Hb1 = (const float*)d_in[14];
    const float* HW2 = (const float*)d_in[15];
    const float* Hb2 = (const float*)d_in[16];
    float* out = (float*)d_out;

    float *h, *a0, *bb0, *a1, *bb1;
    __half *fh, *w1h, *w1l, *w2h, *w2l, *zh;
    cudaGetSymbolAddress((void**)&h,   g_h);
    cudaGetSymbolAddress((void**)&fh,  g_fh);
    cudaGetSymbolAddress((void**)&w1h, g_w1h);
    cudaGetSymbolAddress((void**)&w1l, g_w1l);
    cudaGetSymbolAddress((void**)&w2h, g_w2h);
    cudaGetSymbolAddress((void**)&w2l, g_w2l);
    cudaGetSymbolAddress((void**)&zh,  g_zh);
    cudaGetSymbolAddress((void**)&a0,  g_a0);
    cudaGetSymbolAddress((void**)&bb0, g_bb0);
    cudaGetSymbolAddress((void**)&a1,  g_a1);
    cudaGetSymbolAddress((void**)&bb1, g_bb1);

    cudaFuncSetAttribute(hmma_gemm_kernel<true, true>,
                         cudaFuncAttributeMaxDynamicSharedMemorySize, HM_SMEM);
    cudaFuncSetAttribute(hmma_gemm_kernel<false, false>,
                         cudaFuncAttributeMaxDynamicSharedMemorySize, HM_SMEM);

    // 0) fold BN into alpha/beta
    prep_bn_kernel<<<8, 256>>>(b0, g0, be0, m0, v0, b1, g1, be1, m1, v1);

    // 0b) head weights: transpose to K-major + split to fp16 hi/lo
    transpose_split_kernel<<<dim3(512 / 32, 1024 / 32, 128), dim3(32, 8)>>>(HW1, w1h, w1l, 1024, 512);
    transpose_split_kernel<<<dim3(256 / 32, 512 / 32, 128), dim3(32, 8)>>>(HW2, w2h, w2l, 512, 256);

    // 1) h = relu(BN(x @ W0 + b0))            fp32
    sgemm_kernel<true, false><<<dim3(16, 8), 256>>>(
        x, W0, h, nullptr, 2048, 200, 2048, a0, bb0);

    // 2) feats = relu(BN(h @ W1 + b1))        fp32 -> fp16
    sgemm_kernel<true, true><<<dim3(8, 8), 256>>>(
        h, W1, nullptr, fh, 1024, 2048, 1024, a1, bb1);

    // 3) z[n] = relu(feats @ HW1[n] + Hb1[n]) -> fp16 [n][1024][512]
    hmma_gemm_kernel<true, true><<<dim3(4, 8, 128), 256, HM_SMEM>>>(
        fh, 0LL, 1024,
        w1h, w1l, 512LL * 1024,
        Hb1, 512,
        nullptr, zh, 1024LL * 512, 512, 1024);

    // 4) out[:,n,:] = z[n] @ HW2[n] + Hb2[n]  -> fp32 [1024][128][256]
    hmma_gemm_kernel<false, false><<<dim3(2, 8, 128), 256, HM_SMEM>>>(
        zh, 1024LL * 512, 512,
        w2h, w2l, 256LL * 512,
        Hb2, 256,
        out, nullptr, 256LL, 128 * 256, 512);
}

// round 7
// speedup vs baseline: 6.0087x; 1.9156x over previous
#include <cuda_runtime.h>
#include <cuda_fp16.h>
#include <cstdint>

#define BN_EPS 1e-5f

// ======================= device scratch (no allocs allowed) =================
static __device__ __half g_hh[1024 * 2048];               // trunk hidden hi
static __device__ __half g_hl[1024 * 2048];               // trunk hidden lo
static __device__ __half g_w1th[1024 * 2048];             // W1^T hi [N=1024][K=2048]
static __device__ __half g_w1tl[1024 * 2048];             // W1^T lo
static __device__ __half g_fh[1024 * 1024];               // feats (fp16) [1024][1024]
static __device__ __half g_hw1t[128u * 512u * 1024u];     // HW1^T [n][512][1024] fp16
static __device__ __half g_hw2t[128u * 256u * 512u];      // HW2^T [n][256][512]  fp16
static __device__ __half g_zh[128u * 1024u * 512u];       // z fp16 [n][1024][512]
static __device__ float g_a0[2048], g_bb0[2048];
static __device__ float g_a1[1024], g_bb1[1024];

// ======================= small helpers ======================================
__device__ __forceinline__ uint32_t smem_to_u32(const void* p) {
    uint32_t a;
    asm("{ .reg .u64 t; cvta.to.shared.u64 t, %1; cvt.u32.u64 %0, t; }" : "=r"(a) : "l"(p));
    return a;
}
__device__ __forceinline__ uint32_t swz128(uint32_t off) {
    return off ^ ((off >> 3) & 0x70);
}
__device__ __forceinline__ void cp_async16(uint32_t dst, const void* src) {
    asm volatile("cp.async.cg.shared.global [%0], [%1], 16;" :: "r"(dst), "l"(src));
}
#define CP_COMMIT() asm volatile("cp.async.commit_group;" ::: "memory")
#define CP_WAIT(n)  asm volatile("cp.async.wait_group %0;" :: "n"(n) : "memory")

#define LDMX4(r, addr) \
    asm volatile("ldmatrix.sync.aligned.m8n8.x4.shared.b16 {%0,%1,%2,%3}, [%4];" \
        : "=r"((r)[0]), "=r"((r)[1]), "=r"((r)[2]), "=r"((r)[3]) : "r"(addr))

#define MMA_F16(d, a, b0_, b1_) \
    asm volatile("mma.sync.aligned.m16n8k16.row.col.f32.f16.f16.f32 " \
        "{%0,%1,%2,%3}, {%4,%5,%6,%7}, {%8,%9}, {%0,%1,%2,%3};" \
        : "+f"((d)[0]), "+f"((d)[1]), "+f"((d)[2]), "+f"((d)[3]) \
        : "r"((a)[0]), "r"((a)[1]), "r"((a)[2]), "r"((a)[3]), "r"(b0_), "r"(b1_))

__device__ __forceinline__ uint32_t pack_h2(__half lo16, __half hi16) {
    return ((uint32_t)__half_as_ushort(hi16) << 16) | __half_as_ushort(lo16);
}

// =========================== prep: fold BN into alpha/beta ==================
__global__ void prep_bn_kernel(const float* __restrict__ b0, const float* __restrict__ g0,
                               const float* __restrict__ be0, const float* __restrict__ m0,
                               const float* __restrict__ v0,
                               const float* __restrict__ b1, const float* __restrict__ g1,
                               const float* __restrict__ be1, const float* __restrict__ m1,
                               const float* __restrict__ v1) {
    int i = blockIdx.x * blockDim.x + threadIdx.x;
    if (i < 2048) {
        float a = g0[i] / sqrtf(v0[i] + BN_EPS);
        g_a0[i]  = a;
        g_bb0[i] = be0[i] + (b0[i] - m0[i]) * a;
    }
    if (i < 1024) {
        float a = g1[i] / sqrtf(v1[i] + BN_EPS);
        g_a1[i]  = a;
        g_bb1[i] = be1[i] + (b1[i] - m1[i]) * a;
    }
}

// ====== transpose + fp32 -> fp16 (hi, optional lo) =========================
// in:  [head][R][C] row-major ; out: [head][C][R]
__global__ void transpose_split_kernel(const float* __restrict__ in,
                                       __half* __restrict__ oh,
                                       __half* __restrict__ ol,
                                       int R, int C) {
    __shared__ float t[32][33];
    const long long hoff = (long long)blockIdx.z * R * C;
    in += hoff; oh += hoff;
    if (ol) ol += hoff;
    const int r0 = blockIdx.y * 32, c0 = blockIdx.x * 32;
    const int tx = threadIdx.x, ty = threadIdx.y;
#pragma unroll
    for (int i = 0; i < 4; i++)
        t[ty + i * 8][tx] = in[(long long)(r0 + ty + i * 8) * C + c0 + tx];
    __syncthreads();
#pragma unroll
    for (int i = 0; i < 4; i++) {
        float v = t[tx][ty + i * 8];
        __half h = __float2half(v);
        long long o = (long long)(c0 + ty + i * 8) * R + r0 + tx;
        oh[o] = h;
        if (ol) ol[o] = __float2half(v - __half2float(h));
    }
}

// ============ fp32 SGEMM (stage 1 only), split fp16 hi/lo output ============
__global__ __launch_bounds__(256, 2)
void sgemm_split_kernel(const float* __restrict__ A, const float* __restrict__ B,
                        __half* __restrict__ Ch, __half* __restrict__ Cl,
                        int N, int K, int ldc,
                        const float* __restrict__ alpha, const float* __restrict__ beta) {
    __shared__ float As[8][128];
    __shared__ float Bs[8][128];
    const int tid = threadIdx.x;
    const int tx = tid & 15;
    const int ty = tid >> 4;
    const int rowBase = blockIdx.y * 128;
    const int colBase = blockIdx.x * 128;
    const int aRow = tid >> 1, aCol = (tid & 1) * 4;
    const int bRow = tid >> 5, bCol = (tid & 31) * 4;
    const float* aPtr = A + (long long)(rowBase + aRow) * K + aCol;
    const float* bPtr = B + (long long)bRow * N + colBase + bCol;

    float acc[8][8];
#pragma unroll
    for (int i = 0; i < 8; i++)
#pragma unroll
        for (int j = 0; j < 8; j++) acc[i][j] = 0.0f;

    for (int kt = 0; kt < K; kt += 8) {
        const float4 av = *(const float4*)(aPtr + kt);
        const float4 bv = *(const float4*)(bPtr + (long long)kt * N);
        __syncthreads();
        As[aCol + 0][aRow] = av.x; As[aCol + 1][aRow] = av.y;
        As[aCol + 2][aRow] = av.z; As[aCol + 3][aRow] = av.w;
        *(float4*)&Bs[bRow][bCol] = bv;
        __syncthreads();
#pragma unroll
        for (int k = 0; k < 8; k++) {
            float aF[8], bF[8];
            *(float4*)&aF[0] = *(const float4*)&As[k][ty * 8];
            *(float4*)&aF[4] = *(const float4*)&As[k][ty * 8 + 4];
            *(float4*)&bF[0] = *(const float4*)&Bs[k][tx * 8];
            *(float4*)&bF[4] = *(const float4*)&Bs[k][tx * 8 + 4];
#pragma unroll
            for (int i = 0; i < 8; i++)
#pragma unroll
                for (int j = 0; j < 8; j++)
                    acc[i][j] = fmaf(aF[i], bF[j], acc[i][j]);
        }
    }

    const int cCol = colBase + tx * 8;
    float alj[8], bej[8];
#pragma unroll
    for (int j = 0; j < 8; j += 4) {
        *(float4*)&bej[j] = *(const float4*)(beta + cCol + j);
        *(float4*)&alj[j] = *(const float4*)(alpha + cCol + j);
    }
#pragma unroll
    for (int i = 0; i < 8; i++) {
        const int r = rowBase + ty * 8 + i;
        uint32_t hp[4], lp[4];
#pragma unroll
        for (int j = 0; j < 8; j += 2) {
            float v0 = fmaxf(fmaf(acc[i][j],     alj[j],     bej[j]),     0.0f);
            float v1 = fmaxf(fmaf(acc[i][j + 1], alj[j + 1], bej[j + 1]), 0.0f);
            __half h0 = __float2half(v0), h1 = __float2half(v1);
            hp[j >> 1] = pack_h2(h0, h1);
            lp[j >> 1] = pack_h2(__float2half(v0 - __half2float(h0)),
                                 __float2half(v1 - __half2float(h1)));
        }
        long long o = (long long)r * ldc + cCol;
        *(uint4*)(Ch + o) = make_uint4(hp[0], hp[1], hp[2], hp[3]);
        *(uint4*)(Cl + o) = make_uint4(lp[0], lp[1], lp[2], lp[3]);
    }
}

// ============ unified mma.sync GEMM: optional A/B lo compensation ===========
// C = act( (A[+Al]) @ (B[+Bl])^T * [alpha] + beta )
// Passes: AhBh (+AhBl if SB) (+AlBh if SA). CTA 128x128, warp 32x64, KC=64.
static constexpr int HM_TILE = 16384;   // 128 rows x 128 B (64 fp16 cols)

template <bool SA, bool SB, bool HASALPHA, bool RELU, bool TOHALF>
__global__ __launch_bounds__(256, 2)
void hmma_gemm_kernel(const __half* __restrict__ Ah, const __half* __restrict__ Al,
                      long long sA, int lda,
                      const __half* __restrict__ Bh, const __half* __restrict__ Bl,
                      long long sB,
                      const float* __restrict__ alpha,
                      const float* __restrict__ bias, int sBias,
                      float* __restrict__ Cf, __half* __restrict__ Ch,
                      long long sC, int ldc, int K) {
    constexpr int NT = 2 + (SA ? 1 : 0) + (SB ? 1 : 0);
    constexpr int BUF = NT * HM_TILE;
    constexpr int OFF_AL = HM_TILE;                       // valid iff SA
    constexpr int OFF_B  = (1 + (SA ? 1 : 0)) * HM_TILE;
    constexpr int OFF_BL = OFF_B + HM_TILE;               // valid iff SB

    extern __shared__ char smem[];
    const uint32_t sb = smem_to_u32(smem);
    const int tid = threadIdx.x;
    const int lane = tid & 31;
    const int w = tid >> 5;
    const int wm = (w >> 1) * 32;
    const int wn = (w & 1) * 64;
    const int head = blockIdx.z;
    const int mBase = blockIdx.y * 128;
    const int nBase = blockIdx.x * 128;

    const __half* pA  = Ah + (long long)head * sA + (long long)mBase * lda;
    const __half* pAl = SA ? Al + (long long)head * sA + (long long)mBase * lda : nullptr;
    const __half* pB  = Bh + (long long)head * sB + (long long)nBase * K;
    const __half* pBl = SB ? Bl + (long long)head * sB + (long long)nBase * K : nullptr;

    float acc[2][8][4];
#pragma unroll
    for (int mi = 0; mi < 2; mi++)
#pragma unroll
        for (int n = 0; n < 8; n++)
#pragma unroll
            for (int q = 0; q < 4; q++) acc[mi][n][q] = 0.0f;

    const int nCh = K >> 6;

    auto load_chunk = [&](uint32_t buf, int kB) {
#pragma unroll
        for (int u = tid; u < 1024; u += 256) {
            const int r = u >> 3, c = u & 7;
            const uint32_t sw = swz128((uint32_t)(r * 128 + c * 16));
            cp_async16(buf + sw, pA + (long long)r * lda + kB + c * 8);
            if (SA) cp_async16(buf + OFF_AL + sw, pAl + (long long)r * lda + kB + c * 8);
            cp_async16(buf + OFF_B + sw, pB + (long long)r * K + kB + c * 8);
            if (SB) cp_async16(buf + OFF_BL + sw, pBl + (long long)r * K + kB + c * 8);
        }
    };

    load_chunk(sb, 0);
    CP_COMMIT();

    const int aRowA = wm + (lane & 15);
    const int aRowB = wn + (lane & 15);
    const int cSel  = (lane >> 4);

    for (int c = 0; c < nCh; ++c) {
        if (c + 1 < nCh) {
            load_chunk(sb + ((c + 1) & 1) * BUF, (c + 1) * 64);
            CP_COMMIT();
            CP_WAIT(1);
        } else {
            CP_WAIT(0);
        }
        __syncthreads();

        const uint32_t bA = sb + (c & 1) * BUF;

#pragma unroll
        for (int ks = 0; ks < 4; ks++) {
            const int kc = ks * 2 + cSel;
            uint32_t ah[2][4], al[2][4];
#pragma unroll
            for (int mi = 0; mi < 2; mi++) {
                uint32_t ad = swz128((uint32_t)((aRowA + mi * 16) * 128 + kc * 16));
                LDMX4(ah[mi], bA + ad);
                if (SA) LDMX4(al[mi], bA + OFF_AL + ad);
            }
#pragma unroll
            for (int g = 0; g < 4; g++) {
                uint32_t bh[4], bl[4];
                uint32_t bd = swz128((uint32_t)((aRowB + g * 16) * 128 + kc * 16));
                LDMX4(bh, bA + OFF_B + bd);
                if (SB) LDMX4(bl, bA + OFF_BL + bd);
#pragma unroll
                for (int mi = 0; mi < 2; mi++) {
#pragma unroll
                    for (int s = 0; s < 2; s++) {
                        const int n = g * 2 + s;
                        MMA_F16(acc[mi][n], ah[mi], bh[s], bh[s + 2]);
                        if (SB) MMA_F16(acc[mi][n], ah[mi], bl[s], bl[s + 2]);
                        if (SA) MMA_F16(acc[mi][n], al[mi], bh[s], bh[s + 2]);
                    }
                }
            }
        }
        __syncthreads();
    }

    // -------------------------------- epilogue ------------------------------
    const float* bp = bias + (long long)head * sBias + nBase;
    const float* ap = HASALPHA ? alpha + nBase : nullptr;
#pragma unroll
    for (int mi = 0; mi < 2; mi++) {
        const int r0 = mBase + wm + mi * 16 + (lane >> 2);
#pragma unroll
        for (int n = 0; n < 8; n++) {
            const int colL = wn + n * 8 + (lane & 3) * 2;
            const float b0 = __ldg(bp + colL);
            const float b1 = __ldg(bp + colL + 1);
            float a0c = 1.0f, a1c = 1.0f;
            if (HASALPHA) { a0c = __ldg(ap + colL); a1c = __ldg(ap + colL + 1); }
#pragma unroll
            for (int rr = 0; rr < 2; rr++) {
                float v0 = HASALPHA ? fmaf(acc[mi][n][rr * 2 + 0], a0c, b0)
                                    : acc[mi][n][rr * 2 + 0] + b0;
                float v1 = HASALPHA ? fmaf(acc[mi][n][rr * 2 + 1], a1c, b1)
                                    : acc[mi][n][rr * 2 + 1] + b1;
                if (RELU) { v0 = fmaxf(v0, 0.0f); v1 = fmaxf(v1, 0.0f); }
                const long long o = (long long)head * sC +
                                    (long long)(r0 + rr * 8) * ldc + nBase + colL;
                if (TOHALF) {
                    *(uint32_t*)(Ch + o) = pack_h2(__float2half(v0), __float2half(v1));
                } else {
                    *(float2*)(Cf + o) = make_float2(v0, v1);
                }
            }
        }
    }
}

// ================================ launcher ==================================
extern "C" void kernel_launch(void* const* d_in, const int* in_sizes, int n_in,
                              void* d_out, int out_size) {
    const float* x   = (const float*)d_in[0];
    const float* W0  = (const float*)d_in[1];
    const float* b0  = (const float*)d_in[2];
    const float* g0  = (const float*)d_in[3];
    const float* be0 = (const float*)d_in[4];
    const float* m0  = (const float*)d_in[5];
    const float* v0  = (const float*)d_in[6];
    const float* W1  = (const float*)d_in[7];
    const float* b1  = (const float*)d_in[8];
    const float* g1  = (const float*)d_in[9];
    const float* be1 = (const float*)d_in[10];
    const float* m1  = (const float*)d_in[11];
    const float* v1  = (const float*)d_in[12];
    const float* HW1 = (const float*)d_in[13];
    const float* Hb1 = (const float*)d_in[14];
    const float* HW2 = (const float*)d_in[15];
    const float* Hb2 = (const float*)d_in[16];
    float* out = (float*)d_out;

    float *a0, *bb0, *a1, *bb1;
    __half *hh, *hl, *w1th, *w1tl, *fh, *hw1t, *hw2t, *zh;
    cudaGetSymbolAddress((void**)&hh,   g_hh);
    cudaGetSymbolAddress((void**)&hl,   g_hl);
    cudaGetSymbolAddress((void**)&w1th, g_w1th);
    cudaGetSymbolAddress((void**)&w1tl, g_w1tl);
    cudaGetSymbolAddress((void**)&fh,   g_fh);
    cudaGetSymbolAddress((void**)&hw1t, g_hw1t);
    cudaGetSymbolAddress((void**)&hw2t, g_hw2t);
    cudaGetSymbolAddress((void**)&zh,   g_zh);
    cudaGetSymbolAddress((void**)&a0,   g_a0);
    cudaGetSymbolAddress((void**)&bb0,  g_bb0);
    cudaGetSymbolAddress((void**)&a1,   g_a1);
    cudaGetSymbolAddress((void**)&bb1,  g_bb1);

    // smem limits for the HMMA variants
    cudaFuncSetAttribute(hmma_gemm_kernel<true, true, true, true, true>,
                         cudaFuncAttributeMaxDynamicSharedMemorySize, 2 * 4 * HM_TILE);
    cudaFuncSetAttribute(hmma_gemm_kernel<false, false, false, true, true>,
                         cudaFuncAttributeMaxDynamicSharedMemorySize, 2 * 2 * HM_TILE);
    cudaFuncSetAttribute(hmma_gemm_kernel<false, false, false, false, false>,
                         cudaFuncAttributeMaxDynamicSharedMemorySize, 2 * 2 * HM_TILE);

    // 0) fold BN into alpha/beta
    prep_bn_kernel<<<8, 256>>>(b0, g0, be0, m0, v0, b1, g1, be1, m1, v1);

    // 0b) transposes: W1^T hi/lo ; head weights hi only
    transpose_split_kernel<<<dim3(1024 / 32, 2048 / 32, 1), dim3(32, 8)>>>(
        W1, w1th, w1tl, 2048, 1024);
    transpose_split_kernel<<<dim3(512 / 32, 1024 / 32, 128), dim3(32, 8)>>>(
        HW1, hw1t, nullptr, 1024, 512);
    transpose_split_kernel<<<dim3(256 / 32, 512 / 32, 128), dim3(32, 8)>>>(
        HW2, hw2t, nullptr, 512, 256);

    // 1) h = relu(BN(x @ W0 + b0))  fp32 -> fp16 hi/lo
    sgemm_split_kernel<<<dim3(16, 8), 256>>>(
        x, W0, hh, hl, 2048, 200, 2048, a0, bb0);

    // 2) feats = relu(BN(h @ W1 + b1))  3-pass split HMMA -> fp16
    hmma_gemm_kernel<true, true, true, true, true><<<dim3(8, 8, 1), 256, 2 * 4 * HM_TILE>>>(
        hh, hl, 0LL, 2048,
        w1th, w1tl, 0LL,
        a1, bb1, 0,
        nullptr, fh, 0LL, 1024, 2048);

    // 3) z[n] = relu(feats @ HW1[n] + Hb1[n])  1-pass fp16 -> fp16
    hmma_gemm_kernel<false, false, false, true, true><<<dim3(4, 8, 128), 256, 2 * 2 * HM_TILE>>>(
        fh, nullptr, 0LL, 1024,
        hw1t, nullptr, 512LL * 1024,
        nullptr, Hb1, 512,
        nullptr, zh, 1024LL * 512, 512, 1024);

    // 4) out[:,n,:] = z[n] @ HW2[n] + Hb2[n]  1-pass fp16 -> fp32
    hmma_gemm_kernel<false, false, false, false, false><<<dim3(2, 8, 128), 256, 2 * 2 * HM_TILE>>>(
        zh, nullptr, 1024LL * 512, 512,
        hw2t, nullptr, 256LL * 512,
        nullptr, Hb2, 256,
        out, nullptr, 256LL, 128 * 256, 512);
}

// round 8
// speedup vs baseline: 7.1289x; 1.1864x over previous
#include <cuda_runtime.h>
#include <cuda_fp16.h>
#include <cstdint>

#define BN_EPS 1e-5f

// ======================= device scratch (no allocs allowed) =================
static __device__ __half g_xh[1024 * 256];                // x hi, K padded to 256
static __device__ __half g_xl[1024 * 256];                // x lo
static __device__ __half g_w0th[2048 * 256];              // W0^T hi [2048][256]
static __device__ __half g_w0tl[2048 * 256];              // W0^T lo
static __device__ __half g_hh[1024 * 2048];               // trunk hidden hi
static __device__ __half g_hl[1024 * 2048];               // trunk hidden lo
static __device__ __half g_w1th[1024 * 2048];             // W1^T hi [1024][2048]
static __device__ __half g_w1tl[1024 * 2048];             // W1^T lo
static __device__ __half g_fh[1024 * 1024];               // feats fp16
static __device__ __half g_hw1t[128u * 512u * 1024u];     // HW1^T [n][512][1024]
static __device__ __half g_hw2t[128u * 256u * 512u];      // HW2^T [n][256][512]
static __device__ __half g_zh[128u * 1024u * 512u];       // z fp16 [n][1024][512]
static __device__ float g_a0[2048], g_bb0[2048];
static __device__ float g_a1[1024], g_bb1[1024];

// ======================= small helpers ======================================
__device__ __forceinline__ uint32_t smem_to_u32(const void* p) {
    uint32_t a;
    asm("{ .reg .u64 t; cvta.to.shared.u64 t, %1; cvt.u32.u64 %0, t; }" : "=r"(a) : "l"(p));
    return a;
}
__device__ __forceinline__ uint32_t swz128(uint32_t off) {
    return off ^ ((off >> 3) & 0x70);
}
__device__ __forceinline__ void cp_async16(uint32_t dst, const void* src) {
    asm volatile("cp.async.cg.shared.global [%0], [%1], 16;" :: "r"(dst), "l"(src));
}
#define CP_COMMIT() asm volatile("cp.async.commit_group;" ::: "memory")
#define CP_WAIT(n)  asm volatile("cp.async.wait_group %0;" :: "n"(n) : "memory")

#define LDMX4(r, addr) \
    asm volatile("ldmatrix.sync.aligned.m8n8.x4.shared.b16 {%0,%1,%2,%3}, [%4];" \
        : "=r"((r)[0]), "=r"((r)[1]), "=r"((r)[2]), "=r"((r)[3]) : "r"(addr))

#define MMA_F16(d, a, b0_, b1_) \
    asm volatile("mma.sync.aligned.m16n8k16.row.col.f32.f16.f16.f32 " \
        "{%0,%1,%2,%3}, {%4,%5,%6,%7}, {%8,%9}, {%0,%1,%2,%3};" \
        : "+f"((d)[0]), "+f"((d)[1]), "+f"((d)[2]), "+f"((d)[3]) \
        : "r"((a)[0]), "r"((a)[1]), "r"((a)[2]), "r"((a)[3]), "r"(b0_), "r"(b1_))

__device__ __forceinline__ uint32_t pack_h2(__half lo16, __half hi16) {
    return ((uint32_t)__half_as_ushort(hi16) << 16) | __half_as_ushort(lo16);
}

// ================= fused prep: BN fold + converts + transposes ==============
// 64x64-tile transpose-split: in [R][C] fp32 -> out [C][Rpad] fp16 hi(/lo),
// rows >= R padded with 0. Requires C%64==0, Rpad%64==0.
__device__ __forceinline__ void tp64(const float* __restrict__ in,
                                     __half* __restrict__ oh, __half* __restrict__ ol,
                                     int R, int C, int Rpad, int r0, int c0,
                                     float* t, int tid) {
#pragma unroll
    for (int k = 0; k < 4; k++) {
        const int u = tid + k * 256;
        const int r = u >> 4;
        const int cq = (u & 15) * 4;
        const int gr = r0 + r;
        float4 v = make_float4(0.f, 0.f, 0.f, 0.f);
        if (gr < R) v = *(const float4*)(in + (long long)gr * C + c0 + cq);
        t[r * 65 + cq]     = v.x;
        t[r * 65 + cq + 1] = v.y;
        t[r * 65 + cq + 2] = v.z;
        t[r * 65 + cq + 3] = v.w;
    }
    __syncthreads();
#pragma unroll
    for (int k = 0; k < 8; k++) {
        const int u = tid + k * 256;
        const int cc = u >> 5;
        const int rq = (u & 31) * 2;
        const float v0 = t[rq * 65 + cc];
        const float v1 = t[(rq + 1) * 65 + cc];
        const __half h0 = __float2half(v0), h1 = __float2half(v1);
        const long long o = (long long)(c0 + cc) * Rpad + r0 + rq;
        *(uint32_t*)(oh + o) = pack_h2(h0, h1);
        if (ol)
            *(uint32_t*)(ol + o) = pack_h2(__float2half(v0 - __half2float(h0)),
                                           __float2half(v1 - __half2float(h1)));
    }
}

// segment layout (block counts): bnfold 8 | xconv 512 | W0T 128 | W1T 512
//                               | HW1T 16384 | HW2T 4096  => total 21640
__global__ __launch_bounds__(256)
void prep_all_kernel(const float* __restrict__ x,
                     const float* __restrict__ W0, const float* __restrict__ W1,
                     const float* __restrict__ HW1, const float* __restrict__ HW2,
                     const float* __restrict__ b0, const float* __restrict__ g0,
                     const float* __restrict__ be0, const float* __restrict__ m0,
                     const float* __restrict__ v0,
                     const float* __restrict__ b1, const float* __restrict__ g1,
                     const float* __restrict__ be1, const float* __restrict__ m1,
                     const float* __restrict__ v1) {
    __shared__ float t[64 * 65];
    const int tid = threadIdx.x;
    const int b = blockIdx.x;

    if (b < 8) {                                    // BN fold
        const int i = b * 256 + tid;
        if (i < 2048) {
            float a = g0[i] / sqrtf(v0[i] + BN_EPS);
            g_a0[i]  = a;
            g_bb0[i] = be0[i] + (b0[i] - m0[i]) * a;
        }
        if (i < 1024) {
            float a = g1[i] / sqrtf(v1[i] + BN_EPS);
            g_a1[i]  = a;
            g_bb1[i] = be1[i] + (b1[i] - m1[i]) * a;
        }
    } else if (b < 520) {                           // x -> xh/xl [1024][256]
        const int u = (b - 8) * 256 + tid;          // 0..131071 (pairs)
        const int row = u >> 7;
        const int c2 = (u & 127) * 2;
        float v0 = (c2     < 200) ? x[row * 200 + c2]     : 0.f;
        float v1 = (c2 + 1 < 200) ? x[row * 200 + c2 + 1] : 0.f;
        __half h0 = __float2half(v0), h1 = __float2half(v1);
        *(uint32_t*)(g_xh + row * 256 + c2) = pack_h2(h0, h1);
        *(uint32_t*)(g_xl + row * 256 + c2) =
            pack_h2(__float2half(v0 - __half2float(h0)),
                    __float2half(v1 - __half2float(h1)));
    } else if (b < 648) {                           // W0T: [200][2048]->[2048][256]
        const int i = b - 520;
        const int by = i >> 5, bx = i & 31;
        tp64(W0, g_w0th, g_w0tl, 200, 2048, 256, by * 64, bx * 64, t, tid);
    } else if (b < 1160) {                          // W1T: [2048][1024]->[1024][2048]
        const int i = b - 648;
        const int by = i >> 4, bx = i & 15;
        tp64(W1, g_w1th, g_w1tl, 2048, 1024, 2048, by * 64, bx * 64, t, tid);
    } else if (b < 17544) {                         // HW1T per head (hi only)
        const int i = b - 1160;
        const int head = i >> 7;
        const int rem = i & 127;
        const int by = rem >> 3, bx = rem & 7;
        tp64(HW1 + (long long)head * 1024 * 512,
             g_hw1t + (long long)head * 512 * 1024, nullptr,
             1024, 512, 1024, by * 64, bx * 64, t, tid);
    } else {                                        // HW2T per head (hi only)
        const int i = b - 17544;
        const int head = i >> 5;
        const int rem = i & 31;
        const int by = rem >> 2, bx = rem & 3;
        tp64(HW2 + (long long)head * 512 * 256,
             g_hw2t + (long long)head * 256 * 512, nullptr,
             512, 256, 512, by * 64, bx * 64, t, tid);
    }
}

// ============ unified mma.sync GEMM, templated tile-N (64/128) ==============
// C = act( (A[+Al]) @ (B[+Bl])^T * [alpha] + beta ) ; passes AhBh(+AhBl)(+AlBh)
// CTA tile 128 x BN, warp tile 32 x (BN/2), K-chunk 64, double-buffered.
// OUTMODE: 0 = fp32, 1 = fp16 hi, 2 = fp16 hi+lo split.
template <int BN, bool SA, bool SB, bool HASALPHA, bool RELU, int OUTMODE>
__global__ __launch_bounds__(256, 2)
void hmma_gemm_kernel(const __half* __restrict__ Ah, const __half* __restrict__ Al,
                      long long sA, int lda,
                      const __half* __restrict__ Bh, const __half* __restrict__ Bl,
                      long long sB,
                      const float* __restrict__ alpha,
                      const float* __restrict__ bias, int sBias,
                      float* __restrict__ Cf, __half* __restrict__ Ch,
                      __half* __restrict__ Cl,
                      long long sC, int ldc, int K) {
    constexpr int TA = 16384;                 // 128 rows x 128 B
    constexpr int TB = BN * 128;
    constexpr int OFF_AL = TA;                // iff SA
    constexpr int OFF_B  = (SA ? 2 : 1) * TA;
    constexpr int OFF_BL = OFF_B + TB;        // iff SB
    constexpr int BUF = OFF_B + (SB ? 2 : 1) * TB;
    constexpr int NF = BN / 16;               // n-fragments per warp
    constexpr int NG = BN / 32;               // ldmatrix groups per warp

    extern __shared__ char smem[];
    const uint32_t sb = smem_to_u32(smem);
    const int tid = threadIdx.x;
    const int lane = tid & 31;
    const int w = tid >> 5;
    const int wm = (w >> 1) * 32;
    const int wn = (w & 1) * (BN / 2);
    const int head = blockIdx.z;
    const int mBase = blockIdx.y * 128;
    const int nBase = blockIdx.x * BN;

    const __half* pA  = Ah + (long long)head * sA + (long long)mBase * lda;
    const __half* pAl = SA ? Al + (long long)head * sA + (long long)mBase * lda : nullptr;
    const __half* pB  = Bh + (long long)head * sB + (long long)nBase * K;
    const __half* pBl = SB ? Bl + (long long)head * sB + (long long)nBase * K : nullptr;

    float acc[2][NF][4];
#pragma unroll
    for (int mi = 0; mi < 2; mi++)
#pragma unroll
        for (int n = 0; n < NF; n++)
#pragma unroll
            for (int q = 0; q < 4; q++) acc[mi][n][q] = 0.0f;

    const int nCh = K >> 6;

    auto load_chunk = [&](uint32_t buf, int kB) {
#pragma unroll
        for (int u = tid; u < 1024; u += 256) {       // A rows: 128
            const int r = u >> 3, c = u & 7;
            const uint32_t sw = swz128((uint32_t)(r * 128 + c * 16));
            cp_async16(buf + sw, pA + (long long)r * lda + kB + c * 8);
            if (SA) cp_async16(buf + OFF_AL + sw, pAl + (long long)r * lda + kB + c * 8);
        }
#pragma unroll
        for (int u = tid; u < BN * 8; u += 256) {     // B rows: BN
            const int r = u >> 3, c = u & 7;
            const uint32_t sw = swz128((uint32_t)(r * 128 + c * 16));
            cp_async16(buf + OFF_B + sw, pB + (long long)r * K + kB + c * 8);
            if (SB) cp_async16(buf + OFF_BL + sw, pBl + (long long)r * K + kB + c * 8);
        }
    };

    load_chunk(sb, 0);
    CP_COMMIT();

    const int aRowA = wm + (lane & 15);
    const int aRowB = wn + (lane & 15);
    const int cSel  = (lane >> 4);

    for (int c = 0; c < nCh; ++c) {
        if (c + 1 < nCh) {
            load_chunk(sb + ((c + 1) & 1) * BUF, (c + 1) * 64);
            CP_COMMIT();
            CP_WAIT(1);
        } else {
            CP_WAIT(0);
        }
        __syncthreads();

        const uint32_t bA = sb + (c & 1) * BUF;

#pragma unroll
        for (int ks = 0; ks < 4; ks++) {
            const int kc = ks * 2 + cSel;
            uint32_t ah[2][4], al[2][4];
#pragma unroll
            for (int mi = 0; mi < 2; mi++) {
                uint32_t ad = swz128((uint32_t)((aRowA + mi * 16) * 128 + kc * 16));
                LDMX4(ah[mi], bA + ad);
                if (SA) LDMX4(al[mi], bA + OFF_AL + ad);
            }
#pragma unroll
            for (int g = 0; g < NG; g++) {
                uint32_t bh[4], bl[4];
                uint32_t bd = swz128((uint32_t)((aRowB + g * 16) * 128 + kc * 16));
                LDMX4(bh, bA + OFF_B + bd);
                if (SB) LDMX4(bl, bA + OFF_BL + bd);
#pragma unroll
                for (int mi = 0; mi < 2; mi++) {
#pragma unroll
                    for (int s = 0; s < 2; s++) {
                        const int n = g * 2 + s;
                        MMA_F16(acc[mi][n], ah[mi], bh[s], bh[s + 2]);
                        if (SB) MMA_F16(acc[mi][n], ah[mi], bl[s], bl[s + 2]);
                        if (SA) MMA_F16(acc[mi][n], al[mi], bh[s], bh[s + 2]);
                    }
                }
            }
        }
        __syncthreads();
    }

    // -------------------------------- epilogue ------------------------------
    const float* bp = bias + (long long)head * sBias + nBase;
    const float* ap = HASALPHA ? alpha + nBase : nullptr;
#pragma unroll
    for (int mi = 0; mi < 2; mi++) {
        const int r0 = mBase + wm + mi * 16 + (lane >> 2);
#pragma unroll
        for (int n = 0; n < NF; n++) {
            const int colL = wn + n * 8 + (lane & 3) * 2;
            const float b0 = __ldg(bp + colL);
            const float b1 = __ldg(bp + colL + 1);
            float a0c = 1.0f, a1c = 1.0f;
            if (HASALPHA) { a0c = __ldg(ap + colL); a1c = __ldg(ap + colL + 1); }
#pragma unroll
            for (int rr = 0; rr < 2; rr++) {
                float v0 = HASALPHA ? fmaf(acc[mi][n][rr * 2 + 0], a0c, b0)
                                    : acc[mi][n][rr * 2 + 0] + b0;
                float v1 = HASALPHA ? fmaf(acc[mi][n][rr * 2 + 1], a1c, b1)
                                    : acc[mi][n][rr * 2 + 1] + b1;
                if (RELU) { v0 = fmaxf(v0, 0.0f); v1 = fmaxf(v1, 0.0f); }
                const long long o = (long long)head * sC +
                                    (long long)(r0 + rr * 8) * ldc + nBase + colL;
                if (OUTMODE == 0) {
                    *(float2*)(Cf + o) = make_float2(v0, v1);
                } else if (OUTMODE == 1) {
                    *(uint32_t*)(Ch + o) = pack_h2(__float2half(v0), __float2half(v1));
                } else {
                    __half h0 = __float2half(v0), h1 = __float2half(v1);
                    *(uint32_t*)(Ch + o) = pack_h2(h0, h1);
                    *(uint32_t*)(Cl + o) =
                        pack_h2(__float2half(v0 - __half2float(h0)),
                                __float2half(v1 - __half2float(h1)));
                }
            }
        }
    }
}

// ================================ launcher ==================================
extern "C" void kernel_launch(void* const* d_in, const int* in_sizes, int n_in,
                              void* d_out, int out_size) {
    const float* x   = (const float*)d_in[0];
    const float* W0  = (const float*)d_in[1];
    const float* b0  = (const float*)d_in[2];
    const float* g0  = (const float*)d_in[3];
    const float* be0 = (const float*)d_in[4];
    const float* m0  = (const float*)d_in[5];
    const float* v0  = (const float*)d_in[6];
    const float* W1  = (const float*)d_in[7];
    const float* b1  = (const float*)d_in[8];
    const float* g1  = (const float*)d_in[9];
    const float* be1 = (const float*)d_in[10];
    const float* m1  = (const float*)d_in[11];
    const float* v1  = (const float*)d_in[12];
    const float* HW1 = (const float*)d_in[13];
    const float* Hb1 = (const float*)d_in[14];
    const float* HW2 = (const float*)d_in[15];
    const float* Hb2 = (const float*)d_in[16];
    float* out = (float*)d_out;

    float *a0, *bb0, *a1, *bb1;
    __half *xh, *xl, *w0th, *w0tl, *hh, *hl, *w1th, *w1tl, *fh, *hw1t, *hw2t, *zh;
    cudaGetSymbolAddress((void**)&xh,   g_xh);
    cudaGetSymbolAddress((void**)&xl,   g_xl);
    cudaGetSymbolAddress((void**)&w0th, g_w0th);
    cudaGetSymbolAddress((void**)&w0tl, g_w0tl);
    cudaGetSymbolAddress((void**)&hh,   g_hh);
    cudaGetSymbolAddress((void**)&hl,   g_hl);
    cudaGetSymbolAddress((void**)&w1th, g_w1th);
    cudaGetSymbolAddress((void**)&w1tl, g_w1tl);
    cudaGetSymbolAddress((void**)&fh,   g_fh);
    cudaGetSymbolAddress((void**)&hw1t, g_hw1t);
    cudaGetSymbolAddress((void**)&hw2t, g_hw2t);
    cudaGetSymbolAddress((void**)&zh,   g_zh);
    cudaGetSymbolAddress((void**)&a0,   g_a0);
    cudaGetSymbolAddress((void**)&bb0,  g_bb0);
    cudaGetSymbolAddress((void**)&a1,   g_a1);
    cudaGetSymbolAddress((void**)&bb1,  g_bb1);

    // dynamic smem limits per instantiation
    cudaFuncSetAttribute(hmma_gemm_kernel<64, true, true, true, true, 2>,
                         cudaFuncAttributeMaxDynamicSharedMemorySize, 98304);
    cudaFuncSetAttribute(hmma_gemm_kernel<64, true, true, true, true, 1>,
                         cudaFuncAttributeMaxDynamicSharedMemorySize, 98304);
    cudaFuncSetAttribute(hmma_gemm_kernel<128, false, false, false, true, 1>,
                         cudaFuncAttributeMaxDynamicSharedMemorySize, 65536);
    cudaFuncSetAttribute(hmma_gemm_kernel<128, false, false, false, false, 0>,
                         cudaFuncAttributeMaxDynamicSharedMemorySize, 65536);

    // 0) single fused prep launch
    prep_all_kernel<<<21640, 256>>>(x, W0, W1, HW1, HW2,
                                    b0, g0, be0, m0, v0, b1, g1, be1, m1, v1);

    // 1) h = relu(BN(x @ W0 + b0))   3-pass split HMMA -> fp16 hi/lo
    hmma_gemm_kernel<64, true, true, true, true, 2><<<dim3(32, 8, 1), 256, 98304>>>(
        xh, xl, 0LL, 256,
        w0th, w0tl, 0LL,
        a0, bb0, 0,
        nullptr, hh, hl, 0LL, 2048, 256);

    // 2) feats = relu(BN(h @ W1 + b1))  3-pass split HMMA -> fp16
    hmma_gemm_kernel<64, true, true, true, true, 1><<<dim3(16, 8, 1), 256, 98304>>>(
        hh, hl, 0LL, 2048,
        w1th, w1tl, 0LL,
        a1, bb1, 0,
        nullptr, fh, nullptr, 0LL, 1024, 2048);

    // 3) z[n] = relu(feats @ HW1[n] + Hb1[n])  1-pass fp16 -> fp16
    hmma_gemm_kernel<128, false, false, false, true, 1><<<dim3(4, 8, 128), 256, 65536>>>(
        fh, nullptr, 0LL, 1024,
        hw1t, nullptr, 512LL * 1024,
        nullptr, Hb1, 512,
        nullptr, zh, nullptr, 1024LL * 512, 512, 1024);

    // 4) out[:,n,:] = z[n] @ HW2[n] + Hb2[n]  1-pass fp16 -> fp32
    hmma_gemm_kernel<128, false, false, false, false, 0><<<dim3(2, 8, 128), 256, 65536>>>(
        zh, nullptr, 1024LL * 512, 512,
        hw2t, nullptr, 256LL * 512,
        nullptr, Hb2, 256,
        out, nullptr, nullptr, 256LL, 128 * 256, 512);
}